// round 2
// baseline (speedup 1.0000x reference)
#include <cuda_runtime.h>

#define H 256
#define NA 100000
#define NB 250000
#define NM 2000
#define AF 133
#define BF 147
#define MAXNB 6
#define AH (AF + H)   // 389

typedef unsigned long long ull;
typedef long long ll;

// Scratch (device globals: allocation-guard-safe)
__device__ float g_inp[(ll)NB * H];     // 256 MB
__device__ float g_msg0[(ll)NB * H];    // 256 MB
__device__ float g_msg1[(ll)NB * H];    // 256 MB
__device__ float g_amsg[(ll)NA * H];    // 102 MB
__device__ float g_molsum[NM * H];
__device__ float g_wsum[NM];

// ---------------- packed f32x2 helpers (FFMA2 path, sm_103a) ----------------
__device__ __forceinline__ ull pack2(float lo, float hi) {
    ull r; asm("mov.b64 %0, {%1,%2};" : "=l"(r) : "f"(lo), "f"(hi)); return r;
}
__device__ __forceinline__ float2 unpack2(ull v) {
    float2 f; asm("mov.b64 {%0,%1}, %2;" : "=f"(f.x), "=f"(f.y) : "l"(v)); return f;
}
__device__ __forceinline__ void ffma2(ull& d, ull a, ull b) {
    asm("fma.rn.f32x2 %0, %1, %2, %0;" : "+l"(d) : "l"(a), "l"(b));
}

// ---------------- fused GEMM ----------------
struct GArgs {
    const float* A;        // mode0: f_bonds
    const float* W;        // weight [K x 256] row-major
    const int*   b2a;      // mode1
    const int*   b2revb;   // mode1
    const float* amsg;     // mode1/2
    const float* msgcur;   // mode1
    const float* inp;      // mode1 epilogue
    const float* fatoms;   // mode2
    const float* b_o;      // mode2
    const float* w_atoms;  // mode2
    const int*   mol_ids;  // mode2
    float* out0;           // mode0: inp store; mode2: molsum (atomics)
    float* out1;           // mode0: relu msg; mode1: msg_next
    int M, K;
};

template <int MODE>
__global__ __launch_bounds__(256) void gemm_kernel(GArgs g) {
    __shared__ float As[16][132];   // padded: 132*4=528B row, 16B-aligned
    __shared__ float Bs[16][128];

    const int tid  = threadIdx.x;
    const int bm   = blockIdx.x * 128;
    const int bn   = blockIdx.y * 128;
    const int trow = (tid >> 4) * 8;
    const int tcol = (tid & 15) * 8;

    ull acc[8][4];
#pragma unroll
    for (int i = 0; i < 8; i++)
#pragma unroll
        for (int j = 0; j < 4; j++) acc[i][j] = 0ull;

    // A-tile loader geometry: thread covers row m, 8 consecutive k
    const int  m      = tid >> 1;
    const int  kk     = (tid & 1) * 8;
    const int  growl  = bm + m;
    const bool rvalid = growl < g.M;

    const float* ap1 = nullptr;
    const float* ap2 = nullptr;
    if (MODE == 1 && rvalid) {
        ap1 = g.amsg   + (ll)g.b2a[growl]   * H;
        ap2 = g.msgcur + (ll)g.b2revb[growl] * H;
    }

    const int KT = (g.K + 15) / 16;
    for (int kt = 0; kt < KT; kt++) {
        const int k0 = kt * 16;

        // ---- load A tile ----
        if (MODE == 1) {
            if (rvalid) {
                float4 x0 = *(const float4*)(ap1 + k0 + kk);
                float4 x1 = *(const float4*)(ap1 + k0 + kk + 4);
                float4 y0 = *(const float4*)(ap2 + k0 + kk);
                float4 y1 = *(const float4*)(ap2 + k0 + kk + 4);
                As[kk + 0][m] = x0.x - y0.x; As[kk + 1][m] = x0.y - y0.y;
                As[kk + 2][m] = x0.z - y0.z; As[kk + 3][m] = x0.w - y0.w;
                As[kk + 4][m] = x1.x - y1.x; As[kk + 5][m] = x1.y - y1.y;
                As[kk + 6][m] = x1.z - y1.z; As[kk + 7][m] = x1.w - y1.w;
            } else {
#pragma unroll
                for (int i = 0; i < 8; i++) As[kk + i][m] = 0.f;
            }
        } else {
#pragma unroll
            for (int i = 0; i < 8; i++) {
                int gk = k0 + kk + i;
                float v = 0.f;
                if (rvalid && gk < g.K) {
                    if (MODE == 0) v = g.A[(ll)growl * BF + gk];
                    else v = (gk < AF) ? g.fatoms[(ll)growl * AF + gk]
                                       : g.amsg[(ll)growl * H + (gk - AF)];
                }
                As[kk + i][m] = v;
            }
        }
        // ---- load B tile (coalesced) ----
#pragma unroll
        for (int i = 0; i < 8; i++) {
            int e = tid + i * 256;
            int k = e >> 7, n = e & 127;
            int gk = k0 + k;
            Bs[k][n] = (gk < g.K) ? g.W[(ll)gk * H + bn + n] : 0.f;
        }
        __syncthreads();

        // ---- 8x8 micro-tile with packed f32x2 FMA ----
#pragma unroll
        for (int k = 0; k < 16; k++) {
            float4 a0 = *(const float4*)&As[k][trow];
            float4 a1 = *(const float4*)&As[k][trow + 4];
            float4 b0 = *(const float4*)&Bs[k][tcol];
            float4 b1 = *(const float4*)&Bs[k][tcol + 4];
            ull bp0 = pack2(b0.x, b0.y), bp1 = pack2(b0.z, b0.w);
            ull bp2 = pack2(b1.x, b1.y), bp3 = pack2(b1.z, b1.w);
            float av[8] = {a0.x, a0.y, a0.z, a0.w, a1.x, a1.y, a1.z, a1.w};
#pragma unroll
            for (int i = 0; i < 8; i++) {
                ull ap = pack2(av[i], av[i]);
                ffma2(acc[i][0], ap, bp0);
                ffma2(acc[i][1], ap, bp1);
                ffma2(acc[i][2], ap, bp2);
                ffma2(acc[i][3], ap, bp3);
            }
        }
        __syncthreads();
    }

    // ---- epilogue ----
    const int gcol = bn + tcol;
    if (MODE == 2) {
        float bo[8];
#pragma unroll
        for (int j = 0; j < 8; j++) bo[j] = g.b_o[gcol + j];
        int   cur_mol = -1;
        float accv[8];
#pragma unroll
        for (int j = 0; j < 8; j++) accv[j] = 0.f;
#pragma unroll
        for (int i = 0; i < 8; i++) {
            int grow = bm + trow + i;
            if (grow < g.M) {
                int   mol = g.mol_ids[grow];
                float w   = g.w_atoms[grow];
                if (mol != cur_mol) {
                    if (cur_mol >= 0) {
#pragma unroll
                        for (int j = 0; j < 8; j++)
                            atomicAdd(&g.out0[(ll)cur_mol * H + gcol + j], accv[j]);
                    }
                    cur_mol = mol;
#pragma unroll
                    for (int j = 0; j < 8; j++) accv[j] = 0.f;
                }
#pragma unroll
                for (int j = 0; j < 4; j++) {
                    float2 u = unpack2(acc[i][j]);
                    accv[2 * j]     += fmaxf(u.x + bo[2 * j], 0.f) * w;
                    accv[2 * j + 1] += fmaxf(u.y + bo[2 * j + 1], 0.f) * w;
                }
            }
        }
        if (cur_mol >= 0) {
#pragma unroll
            for (int j = 0; j < 8; j++)
                atomicAdd(&g.out0[(ll)cur_mol * H + gcol + j], accv[j]);
        }
    } else {
#pragma unroll
        for (int i = 0; i < 8; i++) {
            int grow = bm + trow + i;
            if (grow >= g.M) continue;
            float v[8];
#pragma unroll
            for (int j = 0; j < 4; j++) {
                float2 u = unpack2(acc[i][j]);
                v[2 * j] = u.x; v[2 * j + 1] = u.y;
            }
            ll off = (ll)grow * H + gcol;
            if (MODE == 0) {
                *(float4*)&g.out0[off]     = make_float4(v[0], v[1], v[2], v[3]);
                *(float4*)&g.out0[off + 4] = make_float4(v[4], v[5], v[6], v[7]);
                *(float4*)&g.out1[off]     = make_float4(fmaxf(v[0], 0.f), fmaxf(v[1], 0.f),
                                                         fmaxf(v[2], 0.f), fmaxf(v[3], 0.f));
                *(float4*)&g.out1[off + 4] = make_float4(fmaxf(v[4], 0.f), fmaxf(v[5], 0.f),
                                                         fmaxf(v[6], 0.f), fmaxf(v[7], 0.f));
            } else {  // MODE 1
                float4 i0 = *(const float4*)&g.inp[off];
                float4 i1 = *(const float4*)&g.inp[off + 4];
                *(float4*)&g.out1[off]     = make_float4(fmaxf(v[0] + i0.x, 0.f), fmaxf(v[1] + i0.y, 0.f),
                                                         fmaxf(v[2] + i0.z, 0.f), fmaxf(v[3] + i0.w, 0.f));
                *(float4*)&g.out1[off + 4] = make_float4(fmaxf(v[4] + i1.x, 0.f), fmaxf(v[5] + i1.y, 0.f),
                                                         fmaxf(v[6] + i1.z, 0.f), fmaxf(v[7] + i1.w, 0.f));
            }
        }
    }
}

// ---------------- per-atom weighted neighbor-message gather ----------------
__global__ __launch_bounds__(256) void gather_kernel(const float* __restrict__ msg,
                                                     const float* __restrict__ w_bonds,
                                                     const int* __restrict__ a2b,
                                                     float* __restrict__ amsg) {
    int tid  = threadIdx.x;
    int a    = blockIdx.x * 4 + (tid >> 6);  // 4 atoms/block, 64 threads each
    int lane = tid & 63;
    float4 s = make_float4(0.f, 0.f, 0.f, 0.f);
#pragma unroll
    for (int j = 0; j < MAXNB; j++) {
        int   b = a2b[a * MAXNB + j];
        float w = w_bonds[b];
        float4 mv = *(const float4*)&msg[(ll)b * H + lane * 4];
        s.x += w * mv.x; s.y += w * mv.y; s.z += w * mv.z; s.w += w * mv.w;
    }
    *(float4*)&amsg[(ll)a * H + lane * 4] = s;
}

__global__ void zero_kernel(float* molsum, float* wsum) {
    int i = blockIdx.x * 256 + threadIdx.x;
    if (i < NM * H) molsum[i] = 0.f;
    if (i < NM) wsum[i] = 0.f;
}

__global__ void wsum_kernel(const float* __restrict__ w_atoms,
                            const int* __restrict__ mol_ids,
                            float* __restrict__ wsum) {
    int i = blockIdx.x * 256 + threadIdx.x;
    if (i < NA) atomicAdd(&wsum[mol_ids[i]], w_atoms[i]);
}

__global__ void finalize_kernel(const float* __restrict__ molsum,
                                const float* __restrict__ wsum,
                                const float* __restrict__ deg,
                                float* __restrict__ out) {
    int m = blockIdx.x, hc = threadIdx.x;
    float w = wsum[m];
    float v = (w > 0.f) ? molsum[m * H + hc] / w : 0.f;
    out[m * H + hc] = deg[m] * v;
}

extern "C" void kernel_launch(void* const* d_in, const int* in_sizes, int n_in,
                              void* d_out, int out_size) {
    const float* f_atoms = (const float*)d_in[0];
    const float* f_bonds = (const float*)d_in[1];
    const float* w_atoms = (const float*)d_in[2];
    const float* w_bonds = (const float*)d_in[3];
    const float* W_i     = (const float*)d_in[4];
    const float* W_h     = (const float*)d_in[5];
    const float* W_o     = (const float*)d_in[6];
    const float* b_o     = (const float*)d_in[7];
    const float* deg     = (const float*)d_in[8];
    const int*   a2b     = (const int*)d_in[9];
    const int*   b2a     = (const int*)d_in[10];
    const int*   b2revb  = (const int*)d_in[11];
    const int*   mol_ids = (const int*)d_in[12];

    float *p_inp, *p_msg0, *p_msg1, *p_amsg, *p_molsum, *p_wsum;
    cudaGetSymbolAddress((void**)&p_inp, g_inp);
    cudaGetSymbolAddress((void**)&p_msg0, g_msg0);
    cudaGetSymbolAddress((void**)&p_msg1, g_msg1);
    cudaGetSymbolAddress((void**)&p_amsg, g_amsg);
    cudaGetSymbolAddress((void**)&p_molsum, g_molsum);
    cudaGetSymbolAddress((void**)&p_wsum, g_wsum);

    zero_kernel<<<NM, 256>>>(p_molsum, p_wsum);

    dim3 gb((NB + 127) / 128, 2);
    dim3 ga((NA + 127) / 128, 2);

    // input layer: inp = f_bonds @ W_i ; msg0 = relu(inp)
    GArgs g0 = {};
    g0.A = f_bonds; g0.W = W_i; g0.out0 = p_inp; g0.out1 = p_msg0;
    g0.M = NB; g0.K = BF;
    gemm_kernel<0><<<gb, 256>>>(g0);

    // depth iter 1
    gather_kernel<<<NA / 4, 256>>>(p_msg0, w_bonds, a2b, p_amsg);
    GArgs g1 = {};
    g1.W = W_h; g1.b2a = b2a; g1.b2revb = b2revb;
    g1.amsg = p_amsg; g1.msgcur = p_msg0; g1.inp = p_inp; g1.out1 = p_msg1;
    g1.M = NB; g1.K = H;
    gemm_kernel<1><<<gb, 256>>>(g1);

    // depth iter 2
    gather_kernel<<<NA / 4, 256>>>(p_msg1, w_bonds, a2b, p_amsg);
    GArgs g2 = g1;
    g2.msgcur = p_msg1; g2.out1 = p_msg0;
    gemm_kernel<1><<<gb, 256>>>(g2);

    // readout gather
    gather_kernel<<<NA / 4, 256>>>(p_msg0, w_bonds, a2b, p_amsg);

    wsum_kernel<<<(NA + 255) / 256, 256>>>(w_atoms, mol_ids, p_wsum);

    // atom readout GEMM + fused segment-sum
    GArgs g3 = {};
    g3.fatoms = f_atoms; g3.amsg = p_amsg; g3.W = W_o; g3.b_o = b_o;
    g3.w_atoms = w_atoms; g3.mol_ids = mol_ids; g3.out0 = p_molsum;
    g3.M = NA; g3.K = AH;
    gemm_kernel<2><<<ga, 256>>>(g3);

    finalize_kernel<<<NM, 256>>>(p_molsum, p_wsum, deg, (float*)d_out);
}